// round 2
// baseline (speedup 1.0000x reference)
#include <cuda_runtime.h>
#include <cuda_bf16.h>

#define HGT 512
#define WID 512
#define BX  32
#define BY  8
#define NTHREADS (BX*BY)

// compare-exchange: a<-min, b<-max  (FMNMX x2 on alu pipe)
#define CE(a,b) { float lo_ = fminf(a,b); float hi_ = fmaxf(a,b); a = lo_; b = hi_; }

__global__ __launch_bounds__(NTHREADS) void morph2d_kernel(
    const float* __restrict__ x,
    const float* __restrict__ se,
    const float* __restrict__ rnk,
    float* __restrict__ out)
{
    __shared__ float tile[BY + 2][BX + 2];   // 10 x 34
    __shared__ float s_w[9];
    __shared__ float s_se[9];

    const int tx  = threadIdx.x;
    const int ty  = threadIdx.y;
    const int tid = ty * BX + tx;
    const int b   = blockIdx.z;
    const int x0  = blockIdx.x * BX;
    const int y0  = blockIdx.y * BY;

    const float* img = x + (size_t)b * (HGT * WID);

    // per-block softmax numerators + se into smem
    if (tid < 9) {
        s_w[tid]  = __expf(rnk[tid]);
        s_se[tid] = se[tid];
    }

    // cooperative halo tile load (zero-padded SAME)
    #pragma unroll
    for (int i = tid; i < (BY + 2) * (BX + 2); i += NTHREADS) {
        int r  = i / (BX + 2);
        int c  = i - r * (BX + 2);
        int gy = y0 + r - 1;
        int gx = x0 + c - 1;
        float v = 0.0f;
        if ((unsigned)gy < HGT && (unsigned)gx < WID)
            v = __ldg(&img[gy * WID + gx]);
        tile[r][c] = v;
    }
    __syncthreads();

    // normalize softmax once per block
    if (tid == 0) {
        float s = 0.0f;
        #pragma unroll
        for (int i = 0; i < 9; i++) s += s_w[i];
        float inv = __fdividef(1.0f, s);
        #pragma unroll
        for (int i = 0; i < 9; i++) s_w[i] *= inv;
    }
    __syncthreads();

    // gather 3x3 window (conflict-free: lanes are consecutive in a row) and
    // apply SE weights (row-major window order: dy major, dx minor)
    float v0 = tile[ty + 0][tx + 0] * s_se[0];
    float v1 = tile[ty + 0][tx + 1] * s_se[1];
    float v2 = tile[ty + 0][tx + 2] * s_se[2];
    float v3 = tile[ty + 1][tx + 0] * s_se[3];
    float v4 = tile[ty + 1][tx + 1] * s_se[4];
    float v5 = tile[ty + 1][tx + 2] * s_se[5];
    float v6 = tile[ty + 2][tx + 0] * s_se[6];
    float v7 = tile[ty + 2][tx + 1] * s_se[7];
    float v8 = tile[ty + 2][tx + 2] * s_se[8];

    // optimal 25-comparator sorting network for n=9 (ascending)
    CE(v0,v3) CE(v1,v7) CE(v2,v5) CE(v4,v8)
    CE(v0,v7) CE(v2,v4) CE(v3,v8) CE(v5,v6)
    CE(v0,v2) CE(v1,v3) CE(v4,v5) CE(v7,v8)
    CE(v1,v4) CE(v3,v6) CE(v5,v7)
    CE(v0,v1) CE(v2,v4) CE(v3,v5) CE(v6,v8)
    CE(v2,v3) CE(v4,v5) CE(v6,v7)
    CE(v1,v2) CE(v3,v4) CE(v5,v6)

    // softmax-weighted sum over sorted window
    float r;
    r = v0 * s_w[0];
    r = fmaf(v1, s_w[1], r);
    r = fmaf(v2, s_w[2], r);
    r = fmaf(v3, s_w[3], r);
    r = fmaf(v4, s_w[4], r);
    r = fmaf(v5, s_w[5], r);
    r = fmaf(v6, s_w[6], r);
    r = fmaf(v7, s_w[7], r);
    r = fmaf(v8, s_w[8], r);

    out[((size_t)b * HGT + (y0 + ty)) * WID + (x0 + tx)] = r;
}

extern "C" void kernel_launch(void* const* d_in, const int* in_sizes, int n_in,
                              void* d_out, int out_size)
{
    const float* x   = (const float*)d_in[0];
    const float* se  = (const float*)d_in[1];
    const float* rnk = (const float*)d_in[2];
    float* out       = (float*)d_out;

    dim3 block(BX, BY);
    dim3 grid(WID / BX, HGT / BY, 32);
    morph2d_kernel<<<grid, block>>>(x, se, rnk, out);
}

// round 3
// speedup vs baseline: 2.2123x; 2.2123x over previous
#include <cuda_runtime.h>
#include <cuda_bf16.h>

#define HGT 512
#define WID 512
#define BX  32
#define BY  4
#define RPT 8                    // rows (pixels) per thread
#define NT  (BX*BY)              // 128 threads
#define TILE_W (BX + 2)          // 34
#define TILE_H (BY*RPT + 2)      // 34

// compare-exchange: a<-min, b<-max  (2x FMNMX, alu pipe)
#define CE(a,b) { float lo_ = fminf(a,b); float hi_ = fmaxf(a,b); a = lo_; b = hi_; }

__global__ __launch_bounds__(NT) void morph2d_kernel(
    const float* __restrict__ x,
    const float* __restrict__ se,
    const float* __restrict__ rnk,
    float* __restrict__ out)
{
    __shared__ float tile[TILE_H][TILE_W];
    __shared__ float s_w[9];     // exp(rank) numerators (unnormalized)
    __shared__ float s_se[9];

    const int tx  = threadIdx.x;
    const int ty  = threadIdx.y;
    const int tid = ty * BX + tx;
    const int bb  = blockIdx.z;
    const int x0  = blockIdx.x * BX;
    const int y0  = blockIdx.y * (BY * RPT);

    const float* img = x + (size_t)bb * (HGT * WID);

    if (tid < 9) {
        s_w[tid]  = __expf(rnk[tid]);
        s_se[tid] = se[tid];
    }

    // cooperative halo tile load (zero-padded SAME)
    #pragma unroll
    for (int i = tid; i < TILE_H * TILE_W; i += NT) {
        int r  = i / TILE_W;
        int c  = i - r * TILE_W;
        int gy = y0 + r - 1;
        int gx = x0 + c - 1;
        float v = 0.0f;
        if ((unsigned)gy < HGT && (unsigned)gx < WID)
            v = __ldg(&img[gy * WID + gx]);
        tile[r][c] = v;
    }
    __syncthreads();

    // hoist weights into registers once per thread (amortized over RPT pixels)
    const float e0 = s_se[0], e1 = s_se[1], e2 = s_se[2];
    const float e3 = s_se[3], e4 = s_se[4], e5 = s_se[5];
    const float e6 = s_se[6], e7 = s_se[7], e8 = s_se[8];
    const float w0 = s_w[0], w1 = s_w[1], w2 = s_w[2];
    const float w3 = s_w[3], w4 = s_w[4], w5 = s_w[5];
    const float w6 = s_w[6], w7 = s_w[7], w8 = s_w[8];
    const float inv = __fdividef(1.0f, ((w0+w1)+(w2+w3))+((w4+w5)+(w6+w7))+w8);

    const int row = ty * RPT;    // first window row in tile for this thread

    // rolling raw window rows: a = top, b = mid, c = bottom
    float a0 = tile[row + 0][tx], a1 = tile[row + 0][tx + 1], a2 = tile[row + 0][tx + 2];
    float b0 = tile[row + 1][tx], b1 = tile[row + 1][tx + 1], b2 = tile[row + 1][tx + 2];

    float* outp = out + (((size_t)bb * HGT) + (y0 + row)) * WID + (x0 + tx);

    #pragma unroll
    for (int yy = 0; yy < RPT; yy++) {
        float c0 = tile[row + 2 + yy][tx];
        float c1 = tile[row + 2 + yy][tx + 1];
        float c2 = tile[row + 2 + yy][tx + 2];

        // apply SE weights (row-major window order)
        float v0 = a0 * e0, v1 = a1 * e1, v2 = a2 * e2;
        float v3 = b0 * e3, v4 = b1 * e4, v5 = b2 * e5;
        float v6 = c0 * e6, v7 = c1 * e7, v8 = c2 * e8;

        // optimal 25-comparator sorting network for n=9 (ascending)
        CE(v0,v3) CE(v1,v7) CE(v2,v5) CE(v4,v8)
        CE(v0,v7) CE(v2,v4) CE(v3,v8) CE(v5,v6)
        CE(v0,v2) CE(v1,v3) CE(v4,v5) CE(v7,v8)
        CE(v1,v4) CE(v3,v6) CE(v5,v7)
        CE(v0,v1) CE(v2,v4) CE(v3,v5) CE(v6,v8)
        CE(v2,v3) CE(v4,v5) CE(v6,v7)
        CE(v1,v2) CE(v3,v4) CE(v5,v6)

        // dot with unnormalized softmax weights, normalize once at the end
        float r;
        r = v0 * w0;
        r = fmaf(v1, w1, r);
        r = fmaf(v2, w2, r);
        r = fmaf(v3, w3, r);
        r = fmaf(v4, w4, r);
        r = fmaf(v5, w5, r);
        r = fmaf(v6, w6, r);
        r = fmaf(v7, w7, r);
        r = fmaf(v8, w8, r);

        outp[(size_t)yy * WID] = r * inv;

        // roll the window down
        a0 = b0; a1 = b1; a2 = b2;
        b0 = c0; b1 = c1; b2 = c2;
    }
}

extern "C" void kernel_launch(void* const* d_in, const int* in_sizes, int n_in,
                              void* d_out, int out_size)
{
    const float* x   = (const float*)d_in[0];
    const float* se  = (const float*)d_in[1];
    const float* rnk = (const float*)d_in[2];
    float* out       = (float*)d_out;

    dim3 block(BX, BY);
    dim3 grid(WID / BX, HGT / (BY * RPT), 32);
    morph2d_kernel<<<grid, block>>>(x, se, rnk, out);
}